// round 6
// baseline (speedup 1.0000x reference)
#include <cuda_runtime.h>
#include <cuda_fp16.h>
#include <stdint.h>
#include <math.h>

#define LAT     128
#define HID     512
#define NSTEPS  50
#define NTH     256
#define MT      32
#define NCTAS   256

#define SHS     520      // H stride in halfs (260 words ≡ 4 mod 32: conflict-free)
#define SWK     24       // W chunk stride in halfs (12 words ≡ 12 mod 32: conflict-free)

// SMEM byte offsets
#define SH_OFF    0                // H: 32 x 520 halfs = 33280 B (layer1 in-place input)
#define SW_OFF    33280            // W double buffer: 2 x 512 x 24 halfs
#define SW_BUF    24576
#define SBIAS_OFF 82432            // f32: b1eff[512] b2[512] b3[512] b4[128]
#define SCONST_OFF 89088           // f32: c1[50] isa[50] sqrtbeta[50]
#define SMEM_TOTAL 89728

// fp16 transposed weights WT[n][k] (K contiguous)
#define WT1_OFF 0                  // [512][256]
#define WT2_OFF 131072             // [512][512]
#define WT3_OFF 393216             // [512][512]
#define WT4_OFF 655360             // [128][512]
#define WT_TOT  720896
__device__ __align__(16) __half g_WT[WT_TOT];

// ---------------- PTX helpers ----------------
__device__ __forceinline__ uint32_t smem_u32(const void* p) {
    uint32_t a;
    asm("{ .reg .u64 t; cvta.to.shared.u64 t, %1; cvt.u32.u64 %0, t; }" : "=r"(a) : "l"(p));
    return a;
}
__device__ __forceinline__ void cpasync16(uint32_t dst, const void* src) {
    asm volatile("cp.async.cg.shared.global [%0], [%1], 16;\n" :: "r"(dst), "l"(src));
}
#define CP_COMMIT() asm volatile("cp.async.commit_group;\n" ::: "memory")
#define CP_WAIT0()  asm volatile("cp.async.wait_group 0;\n" ::: "memory")

__device__ __forceinline__ void mma16816(float d[4], const uint32_t a[4], const uint32_t b[2]) {
    asm volatile(
        "mma.sync.aligned.m16n8k16.row.col.f32.f16.f16.f32 "
        "{%0,%1,%2,%3}, {%4,%5,%6,%7}, {%8,%9}, {%0,%1,%2,%3};\n"
        : "+f"(d[0]), "+f"(d[1]), "+f"(d[2]), "+f"(d[3])
        : "r"(a[0]), "r"(a[1]), "r"(a[2]), "r"(a[3]), "r"(b[0]), "r"(b[1]));
}

// ---------------- JAX threefry + erfinv (bit-proven round 2) ----------------
__device__ __forceinline__ uint32_t rotl32(uint32_t x, uint32_t r) {
    return __funnelshift_l(x, x, r);
}
__device__ __forceinline__ void threefry2x32(uint32_t k0, uint32_t k1,
                                             uint32_t c0, uint32_t c1,
                                             uint32_t& o0, uint32_t& o1) {
    uint32_t ks2 = k0 ^ k1 ^ 0x1BD11BDAu;
    uint32_t x0 = c0 + k0, x1 = c1 + k1;
#define TF_RND(r) { x0 += x1; x1 = rotl32(x1, r); x1 ^= x0; }
    TF_RND(13) TF_RND(15) TF_RND(26) TF_RND(6)
    x0 += k1;  x1 += ks2 + 1u;
    TF_RND(17) TF_RND(29) TF_RND(16) TF_RND(24)
    x0 += ks2; x1 += k0 + 2u;
    TF_RND(13) TF_RND(15) TF_RND(26) TF_RND(6)
    x0 += k0;  x1 += k1 + 3u;
    TF_RND(17) TF_RND(29) TF_RND(16) TF_RND(24)
    x0 += k1;  x1 += ks2 + 4u;
    TF_RND(13) TF_RND(15) TF_RND(26) TF_RND(6)
    x0 += ks2; x1 += k0 + 5u;
#undef TF_RND
    o0 = x0; o1 = x1;
}
__device__ __forceinline__ float erfinv_f32(float x) {
    float w = -log1pf(-x * x), p;
    if (w < 5.0f) {
        w -= 2.5f;
        p = 2.81022636e-08f;
        p = fmaf(p, w, 3.43273939e-07f);  p = fmaf(p, w, -3.5233877e-06f);
        p = fmaf(p, w, -4.39150654e-06f); p = fmaf(p, w, 0.00021858087f);
        p = fmaf(p, w, -0.00125372503f);  p = fmaf(p, w, -0.00417768164f);
        p = fmaf(p, w, 0.246640727f);     p = fmaf(p, w, 1.50140941f);
    } else {
        w = sqrtf(w) - 3.0f;
        p = -0.000200214257f;
        p = fmaf(p, w, 0.000100950558f);  p = fmaf(p, w, 0.00134934322f);
        p = fmaf(p, w, -0.00367342844f);  p = fmaf(p, w, 0.00573950773f);
        p = fmaf(p, w, -0.0076224613f);   p = fmaf(p, w, 0.00943887047f);
        p = fmaf(p, w, 1.00167406f);      p = fmaf(p, w, 2.83297682f);
    }
    return p * x;
}
__device__ __forceinline__ float jax_normal(uint32_t fk0, uint32_t fk1, uint32_t gi) {
    uint32_t o0, o1;
    threefry2x32(fk0, fk1, 0u, gi, o0, o1);
    uint32_t bits = o0 ^ o1;
    float f = __uint_as_float((bits >> 9) | 0x3f800000u) - 1.0f;
    float u = fmaxf(fmaf(f, 2.0f, -0.99999994f), -0.99999994f);
    return 1.4142135623730951f * erfinv_f32(u);
}
__device__ __forceinline__ float gelu_exact(float v) {
    return 0.5f * v * (1.0f + erff(v * 0.7071067811865476f));
}

// ---------------- weight prep: fp32 -> fp16 transposed (K contiguous) -------
__global__ void prep_kernel(const float* __restrict__ W1, const float* __restrict__ W2,
                            const float* __restrict__ W3, const float* __restrict__ W4) {
    int i = blockIdx.x * 256 + threadIdx.x;
    if (i < 512*256) { int n=i/256, k=i%256; g_WT[WT1_OFF+i] = __float2half_rn(W1[k*512+n]); return; }
    i -= 512*256;
    if (i < 512*512) { int n=i/512, k=i%512; g_WT[WT2_OFF+i] = __float2half_rn(W2[k*512+n]); return; }
    i -= 512*512;
    if (i < 512*512) { int n=i/512, k=i%512; g_WT[WT3_OFF+i] = __float2half_rn(W3[k*512+n]); return; }
    i -= 512*512;
    if (i < 128*512) { int n=i/512, k=i%512; g_WT[WT4_OFF+i] = __float2half_rn(W4[k*128+n]); return; }
}

// ---------------- one layer: K=16 chunks, cp.async double-buffered ----------
// Warp tile: 16 rows (m0) x NT*8 cols (n0).
template<int KDIM, int NT, int NWROWS>
__device__ __forceinline__ void layer_mma(char* sm, uint32_t sb,
        const __half* __restrict__ WTg, const __half* A,
        float (&acc)[NT][4], int tid, int gid, int tig, int m0, int n0)
{
    constexpr int CHUNKS = KDIM / 16;
    // prefetch chunk 0 -> buf 0
#pragma unroll
    for (int v = tid; v < NWROWS * 2; v += NTH) {
        int n = v >> 1, kp = v & 1;
        cpasync16(sb + SW_OFF + (uint32_t)(n * SWK + kp * 8) * 2,
                  WTg + (size_t)n * KDIM + kp * 8);
    }
    CP_COMMIT();
    for (int c = 0; c < CHUNKS; ++c) {
        CP_WAIT0();
        __syncthreads();
        if (c + 1 < CHUNKS) {
            uint32_t bo = (uint32_t)(((c + 1) & 1) * SW_BUF);
            const __half* src = WTg + (c + 1) * 16;
#pragma unroll
            for (int v = tid; v < NWROWS * 2; v += NTH) {
                int n = v >> 1, kp = v & 1;
                cpasync16(sb + SW_OFF + bo + (uint32_t)(n * SWK + kp * 8) * 2,
                          src + (size_t)n * KDIM + kp * 8);
            }
            CP_COMMIT();
        }
        const __half* Wb = (const __half*)(sm + SW_OFF + (c & 1) * SW_BUF);
        int k0 = c * 16;
        uint32_t a[4];
        a[0] = *(const uint32_t*)(A + (m0 + gid) * SHS + k0 + tig * 2);
        a[1] = *(const uint32_t*)(A + (m0 + gid + 8) * SHS + k0 + tig * 2);
        a[2] = *(const uint32_t*)(A + (m0 + gid) * SHS + k0 + tig * 2 + 8);
        a[3] = *(const uint32_t*)(A + (m0 + gid + 8) * SHS + k0 + tig * 2 + 8);
#pragma unroll
        for (int nt = 0; nt < NT; ++nt) {
            int n = n0 + nt * 8 + gid;
            uint32_t b[2];
            b[0] = *(const uint32_t*)(Wb + n * SWK + tig * 2);
            b[1] = *(const uint32_t*)(Wb + n * SWK + tig * 2 + 8);
            mma16816(acc[nt], a, b);
        }
    }
    __syncthreads();   // all A/W reads complete before caller's epilogue writes
}

// epilogue: acc + bias -> gelu -> fp16 H (in place is safe after layer_mma sync)
template<int NT>
__device__ __forceinline__ void epi_gelu(float (&acc)[NT][4], __half* Hout,
                                         const float* bias, int m0, int n0,
                                         int gid, int tig)
{
#pragma unroll
    for (int nt = 0; nt < NT; ++nt) {
        int n = n0 + nt * 8 + tig * 2;
        float2 bb = *(const float2*)(bias + n);
        *(__half2*)(Hout + (m0 + gid) * SHS + n) =
            __floats2half2_rn(gelu_exact(acc[nt][0] + bb.x), gelu_exact(acc[nt][1] + bb.y));
        *(__half2*)(Hout + (m0 + gid + 8) * SHS + n) =
            __floats2half2_rn(gelu_exact(acc[nt][2] + bb.x), gelu_exact(acc[nt][3] + bb.y));
    }
}

__global__ void __launch_bounds__(NTH, 2)
diffusion_kernel(const float* __restrict__ condition,
                 const float* __restrict__ x_init,
                 const float* __restrict__ W1, const float* __restrict__ b1,
                 const float* __restrict__ b2, const float* __restrict__ b3,
                 const float* __restrict__ b4, const int* __restrict__ tsp,
                 float* __restrict__ out)
{
    extern __shared__ char sm[];
    __half* H    = (__half*)(sm + SH_OFF);
    float* sBias = (float*)(sm + SBIAS_OFF);
    float* sC    = (float*)(sm + SCONST_OFF);
    uint32_t sb  = smem_u32(sm);

    int tid = threadIdx.x, w = tid >> 5, lane = tid & 31;
    int gid = lane >> 2, tig = lane & 3;
    int m0 = (w & 1) * 16;         // 2 m-tiles of 16 rows
    int nL = (w >> 1) * 128;       // 4 n-blocks for layers 1-3
    int n4 = (w >> 1) * 32;        // 4 n-blocks for layer 4 / x fragment
    int mA = m0 + gid, mB = m0 + gid + 8;
    int grA = blockIdx.x * MT + mA, grB = blockIdx.x * MT + mB;

    if (tid == 0) {
        float acp = 1.0f, bstep = (0.02f - 1e-4f) / 49.0f;
        for (int t = 0; t < NSTEPS; ++t) {
            float beta = fmaf((float)t, bstep, 1e-4f);
            float alpha = 1.0f - beta;
            acp *= alpha;
            sC[t]              = beta / sqrtf(1.0f - acp);
            sC[NSTEPS + t]     = 1.0f / sqrtf(alpha);
            sC[2 * NSTEPS + t] = sqrtf(beta);
        }
    }
    for (int i = tid; i < 512; i += NTH) {
        sBias[512 + i]  = b2[i];
        sBias[1024 + i] = b3[i];
    }
    if (tid < 128) sBias[1536 + tid] = b4[tid];

    // x fragment in registers (C-fragment layout)
    float xr[4][4];
#pragma unroll
    for (int nt = 0; nt < 4; ++nt) {
        int n = n4 + nt * 8 + tig * 2;
        float2 v0 = *(const float2*)(x_init + (size_t)grA * LAT + n);
        float2 v1 = *(const float2*)(x_init + (size_t)grB * LAT + n);
        xr[nt][0] = v0.x; xr[nt][1] = v0.y; xr[nt][2] = v1.x; xr[nt][3] = v1.y;
    }
    float tgt = (*tsp) ? 0.0f : 1.0f;

    for (int t = NSTEPS - 1; t >= 0; --t) {
        float tval = (float)t / (float)NSTEPS;
        // fold t_emb / target columns into layer-1 bias (fp32 exact)
        for (int i = tid; i < 512; i += NTH)
            sBias[i] = b1[i] + tval * W1[256 * HID + i] + tgt * W1[257 * HID + i];

        // rebuild layer-1 input in H[:, 0:256]: x (regs) | condition (L2 reload)
#pragma unroll
        for (int nt = 0; nt < 4; ++nt) {
            int n = n4 + nt * 8 + tig * 2;
            *(__half2*)(H + mA * SHS + n) = __floats2half2_rn(xr[nt][0], xr[nt][1]);
            *(__half2*)(H + mB * SHS + n) = __floats2half2_rn(xr[nt][2], xr[nt][3]);
            float2 c0 = *(const float2*)(condition + (size_t)grA * LAT + n);
            float2 c1 = *(const float2*)(condition + (size_t)grB * LAT + n);
            *(__half2*)(H + mA * SHS + 128 + n) = __floats2half2_rn(c0.x, c0.y);
            *(__half2*)(H + mB * SHS + 128 + n) = __floats2half2_rn(c1.x, c1.y);
        }
        // (layer_mma's first __syncthreads orders these writes before MMA reads)

        float acc[16][4];
#pragma unroll
        for (int i = 0; i < 16; ++i) { acc[i][0]=acc[i][1]=acc[i][2]=acc[i][3]=0.f; }
        layer_mma<256, 16, 512>(sm, sb, g_WT + WT1_OFF, H, acc, tid, gid, tig, m0, nL);
        epi_gelu<16>(acc, H, sBias, m0, nL, gid, tig);

#pragma unroll
        for (int i = 0; i < 16; ++i) { acc[i][0]=acc[i][1]=acc[i][2]=acc[i][3]=0.f; }
        layer_mma<512, 16, 512>(sm, sb, g_WT + WT2_OFF, H, acc, tid, gid, tig, m0, nL);
        epi_gelu<16>(acc, H, sBias + 512, m0, nL, gid, tig);

#pragma unroll
        for (int i = 0; i < 16; ++i) { acc[i][0]=acc[i][1]=acc[i][2]=acc[i][3]=0.f; }
        layer_mma<512, 16, 512>(sm, sb, g_WT + WT3_OFF, H, acc, tid, gid, tig, m0, nL);
        epi_gelu<16>(acc, H, sBias + 1024, m0, nL, gid, tig);

        float a4[4][4];
#pragma unroll
        for (int i = 0; i < 4; ++i) { a4[i][0]=a4[i][1]=a4[i][2]=a4[i][3]=0.f; }
        layer_mma<512, 4, 128>(sm, sb, g_WT + WT4_OFF, H, a4, tid, gid, tig, m0, n4);

        // x update with JAX-exact noise
        uint32_t fk0 = 0, fk1 = 0;
        if (t > 0) threefry2x32(0u, 42u, 0u, (uint32_t)t, fk0, fk1);
        float c1 = sC[t], isa = sC[NSTEPS + t], sbeta = sC[2 * NSTEPS + t];
#pragma unroll
        for (int nt = 0; nt < 4; ++nt) {
            int n = n4 + nt * 8 + tig * 2;
            float2 bb = *(const float2*)(sBias + 1536 + n);
            float np0 = a4[nt][0] + bb.x, np1 = a4[nt][1] + bb.y;
            float np2 = a4[nt][2] + bb.x, np3 = a4[nt][3] + bb.y;
            float z0=0.f, z1=0.f, z2=0.f, z3=0.f;
            if (t > 0) {
                z0 = jax_normal(fk0, fk1, (uint32_t)(grA * LAT + n));
                z1 = jax_normal(fk0, fk1, (uint32_t)(grA * LAT + n + 1));
                z2 = jax_normal(fk0, fk1, (uint32_t)(grB * LAT + n));
                z3 = jax_normal(fk0, fk1, (uint32_t)(grB * LAT + n + 1));
            }
            xr[nt][0] = (xr[nt][0] - c1 * np0) * isa + sbeta * z0;
            xr[nt][1] = (xr[nt][1] - c1 * np1) * isa + sbeta * z1;
            xr[nt][2] = (xr[nt][2] - c1 * np2) * isa + sbeta * z2;
            xr[nt][3] = (xr[nt][3] - c1 * np3) * isa + sbeta * z3;
        }
        __syncthreads();
    }

#pragma unroll
    for (int nt = 0; nt < 4; ++nt) {
        int n = n4 + nt * 8 + tig * 2;
        *(float2*)(out + (size_t)grA * LAT + n) = make_float2(xr[nt][0], xr[nt][1]);
        *(float2*)(out + (size_t)grB * LAT + n) = make_float2(xr[nt][2], xr[nt][3]);
    }
}

extern "C" void kernel_launch(void* const* d_in, const int* in_sizes, int n_in,
                              void* d_out, int out_size) {
    const float* condition = (const float*)d_in[0];
    const float* x_init    = (const float*)d_in[1];
    const float* W1 = (const float*)d_in[2];
    const float* b1 = (const float*)d_in[3];
    const float* W2 = (const float*)d_in[4];
    const float* b2 = (const float*)d_in[5];
    const float* W3 = (const float*)d_in[6];
    const float* b3 = (const float*)d_in[7];
    const float* W4 = (const float*)d_in[8];
    const float* b4 = (const float*)d_in[9];
    const int*   ts = (const int*)d_in[10];
    float* out = (float*)d_out;

    prep_kernel<<<(WT_TOT + 255) / 256, 256>>>(W1, W2, W3, W4);

    cudaFuncSetAttribute(diffusion_kernel,
                         cudaFuncAttributeMaxDynamicSharedMemorySize, SMEM_TOTAL);
    diffusion_kernel<<<NCTAS, NTH, SMEM_TOTAL>>>(
        condition, x_init, W1, b1, b2, b3, b4, ts, out);
}

// round 7
// speedup vs baseline: 1.6115x; 1.6115x over previous
#include <cuda_runtime.h>
#include <cuda_fp16.h>
#include <stdint.h>
#include <math.h>

#define LAT     128
#define HID     512
#define NSTEPS  50
#define NTH     512
#define MT      64
#define NCTAS   128

#define SHS     520      // H stride in halfs (260 words ≡ 4 mod 32: conflict-free)
#define SWK     72       // W chunk stride in halfs (36 words ≡ 4 mod 32: conflict-free)

// SMEM byte offsets
#define SH_OFF    0                // H: 64 x 520 halfs = 66560 B (layer1 reads cols 0..255 in place)
#define SW_OFF    66560            // W double buffer: 2 x 512 x 72 halfs
#define SW_BUF    73728
#define SBIAS_OFF 214016           // f32: b1eff[512] b2[512] b3[512] b4[128]
#define SCONST_OFF 220672          // f32: c1[50] isa[50] sqrtbeta[50]
#define SMEM_TOTAL 221312

// fp16 transposed weights WT[n][k] (K contiguous)
#define WT1_OFF 0                  // [512][256]
#define WT2_OFF 131072             // [512][512]
#define WT3_OFF 393216             // [512][512]
#define WT4_OFF 655360             // [128][512]
#define WT_TOT  720896
__device__ __align__(16) __half g_WT[WT_TOT];

// ---------------- PTX helpers ----------------
__device__ __forceinline__ uint32_t smem_u32(const void* p) {
    uint32_t a;
    asm("{ .reg .u64 t; cvta.to.shared.u64 t, %1; cvt.u32.u64 %0, t; }" : "=r"(a) : "l"(p));
    return a;
}
__device__ __forceinline__ void cpasync16(uint32_t dst, const void* src) {
    asm volatile("cp.async.cg.shared.global [%0], [%1], 16;\n" :: "r"(dst), "l"(src));
}
#define CP_COMMIT() asm volatile("cp.async.commit_group;\n" ::: "memory")
#define CP_WAIT0()  asm volatile("cp.async.wait_group 0;\n" ::: "memory")

__device__ __forceinline__ void mma16816(float d[4], const uint32_t a[4], const uint32_t b[2]) {
    asm volatile(
        "mma.sync.aligned.m16n8k16.row.col.f32.f16.f16.f32 "
        "{%0,%1,%2,%3}, {%4,%5,%6,%7}, {%8,%9}, {%0,%1,%2,%3};\n"
        : "+f"(d[0]), "+f"(d[1]), "+f"(d[2]), "+f"(d[3])
        : "r"(a[0]), "r"(a[1]), "r"(a[2]), "r"(a[3]), "r"(b[0]), "r"(b[1]));
}

// ---------------- JAX threefry + erfinv (bit-proven round 2) ----------------
__device__ __forceinline__ uint32_t rotl32(uint32_t x, uint32_t r) {
    return __funnelshift_l(x, x, r);
}
__device__ __forceinline__ void threefry2x32(uint32_t k0, uint32_t k1,
                                             uint32_t c0, uint32_t c1,
                                             uint32_t& o0, uint32_t& o1) {
    uint32_t ks2 = k0 ^ k1 ^ 0x1BD11BDAu;
    uint32_t x0 = c0 + k0, x1 = c1 + k1;
#define TF_RND(r) { x0 += x1; x1 = rotl32(x1, r); x1 ^= x0; }
    TF_RND(13) TF_RND(15) TF_RND(26) TF_RND(6)
    x0 += k1;  x1 += ks2 + 1u;
    TF_RND(17) TF_RND(29) TF_RND(16) TF_RND(24)
    x0 += ks2; x1 += k0 + 2u;
    TF_RND(13) TF_RND(15) TF_RND(26) TF_RND(6)
    x0 += k0;  x1 += k1 + 3u;
    TF_RND(17) TF_RND(29) TF_RND(16) TF_RND(24)
    x0 += k1;  x1 += ks2 + 4u;
    TF_RND(13) TF_RND(15) TF_RND(26) TF_RND(6)
    x0 += ks2; x1 += k0 + 5u;
#undef TF_RND
    o0 = x0; o1 = x1;
}
__device__ __forceinline__ float erfinv_f32(float x) {
    float w = -log1pf(-x * x), p;
    if (w < 5.0f) {
        w -= 2.5f;
        p = 2.81022636e-08f;
        p = fmaf(p, w, 3.43273939e-07f);  p = fmaf(p, w, -3.5233877e-06f);
        p = fmaf(p, w, -4.39150654e-06f); p = fmaf(p, w, 0.00021858087f);
        p = fmaf(p, w, -0.00125372503f);  p = fmaf(p, w, -0.00417768164f);
        p = fmaf(p, w, 0.246640727f);     p = fmaf(p, w, 1.50140941f);
    } else {
        w = sqrtf(w) - 3.0f;
        p = -0.000200214257f;
        p = fmaf(p, w, 0.000100950558f);  p = fmaf(p, w, 0.00134934322f);
        p = fmaf(p, w, -0.00367342844f);  p = fmaf(p, w, 0.00573950773f);
        p = fmaf(p, w, -0.0076224613f);   p = fmaf(p, w, 0.00943887047f);
        p = fmaf(p, w, 1.00167406f);      p = fmaf(p, w, 2.83297682f);
    }
    return p * x;
}
__device__ __forceinline__ float jax_normal(uint32_t fk0, uint32_t fk1, uint32_t gi) {
    uint32_t o0, o1;
    threefry2x32(fk0, fk1, 0u, gi, o0, o1);
    uint32_t bits = o0 ^ o1;
    float f = __uint_as_float((bits >> 9) | 0x3f800000u) - 1.0f;
    float u = fmaxf(fmaf(f, 2.0f, -0.99999994f), -0.99999994f);
    return 1.4142135623730951f * erfinv_f32(u);
}
__device__ __forceinline__ float gelu_exact(float v) {
    return 0.5f * v * (1.0f + erff(v * 0.7071067811865476f));
}

// ---------------- weight prep: fp32 -> fp16 transposed (K contiguous) -------
__global__ void prep_kernel(const float* __restrict__ W1, const float* __restrict__ W2,
                            const float* __restrict__ W3, const float* __restrict__ W4) {
    int i = blockIdx.x * 256 + threadIdx.x;
    if (i < 512*256) { int n=i/256, k=i%256; g_WT[WT1_OFF+i] = __float2half_rn(W1[k*512+n]); return; }
    i -= 512*256;
    if (i < 512*512) { int n=i/512, k=i%512; g_WT[WT2_OFF+i] = __float2half_rn(W2[k*512+n]); return; }
    i -= 512*512;
    if (i < 512*512) { int n=i/512, k=i%512; g_WT[WT3_OFF+i] = __float2half_rn(W3[k*512+n]); return; }
    i -= 512*512;
    if (i < 128*512) { int n=i/512, k=i%512; g_WT[WT4_OFF+i] = __float2half_rn(W4[k*128+n]); return; }
}

// W chunk loader: [rows x 64 halfs] from WT (row stride kdim) into SW buffer boff
__device__ __forceinline__ void wload(uint32_t sb, uint32_t boff,
                                      const __half* __restrict__ src,
                                      int rows, int kdim, int tid) {
    for (int v = tid; v < rows * 8; v += NTH) {
        int n = v >> 3, kp = v & 7;
        cpasync16(sb + SW_OFF + boff + (uint32_t)(n * SWK + kp * 8) * 2,
                  src + (size_t)n * kdim + kp * 8);
    }
    CP_COMMIT();
}

// ---------------- one layer: K=64 chunks, double-buffered, cross-layer prefetch
// Warp tile: 16 rows (m0) x NT*8 cols (n0). Optionally interleaves RNG (2/chunk).
template<int KDIM, int NT>
__device__ __forceinline__ void layer_mma(char* sm, uint32_t sb,
        const __half* __restrict__ WTg, int rows,
        const __half* __restrict__ WTn, int nrows, int nkdim,
        const __half* A, float (&acc)[NT][4],
        int tid, int gid, int tig, int m0, int n0,
        bool dorng, float* nz, uint32_t fk0, uint32_t fk1, int giA, int giB)
{
    constexpr int C = KDIM / 64;
    for (int c = 0; c < C; ++c) {
        CP_WAIT0();
        __syncthreads();
        if (c + 1 < C)
            wload(sb, (uint32_t)(((c + 1) & 1) * SW_BUF), WTg + (c + 1) * 64, rows, KDIM, tid);
        else
            wload(sb, 0u, WTn, nrows, nkdim, tid);   // next layer's chunk 0 -> buf 0
        const __half* Wb = (const __half*)(sm + SW_OFF + (c & 1) * SW_BUF);
#pragma unroll
        for (int ks = 0; ks < 4; ++ks) {
            int k0 = c * 64 + ks * 16;
            uint32_t a[4];
            a[0] = *(const uint32_t*)(A + (m0 + gid) * SHS + k0 + tig * 2);
            a[1] = *(const uint32_t*)(A + (m0 + gid + 8) * SHS + k0 + tig * 2);
            a[2] = *(const uint32_t*)(A + (m0 + gid) * SHS + k0 + tig * 2 + 8);
            a[3] = *(const uint32_t*)(A + (m0 + gid + 8) * SHS + k0 + tig * 2 + 8);
#pragma unroll
            for (int nt = 0; nt < NT; ++nt) {
                int n = n0 + nt * 8 + gid;
                uint32_t b[2];
                b[0] = *(const uint32_t*)(Wb + n * SWK + ks * 16 + tig * 2);
                b[1] = *(const uint32_t*)(Wb + n * SWK + ks * 16 + tig * 2 + 8);
                mma16816(acc[nt], a, b);
            }
        }
        if (dorng) {   // layer3 only: C=8 chunks x 2 normals = all 16
#pragma unroll
            for (int q = 0; q < 2; ++q) {
                int idx = 2 * c + q;
                int nt = idx >> 2, v = idx & 3;
                int gi = ((v & 2) ? giB : giA) + nt * 8 + tig * 2 + (v & 1);
                nz[idx] = jax_normal(fk0, fk1, (uint32_t)gi);
            }
        }
    }
    __syncthreads();   // all A/W reads complete before caller's epilogue writes
}

// epilogue: acc + bias -> gelu -> fp16 H (in place, safe after layer_mma syncs)
template<int NT>
__device__ __forceinline__ void epi_gelu(float (&acc)[NT][4], __half* Hout,
                                         const float* bias, int m0, int n0,
                                         int gid, int tig)
{
#pragma unroll
    for (int nt = 0; nt < NT; ++nt) {
        int n = n0 + nt * 8 + tig * 2;
        float2 bb = *(const float2*)(bias + n);
        *(__half2*)(Hout + (m0 + gid) * SHS + n) =
            __floats2half2_rn(gelu_exact(acc[nt][0] + bb.x), gelu_exact(acc[nt][1] + bb.y));
        *(__half2*)(Hout + (m0 + gid + 8) * SHS + n) =
            __floats2half2_rn(gelu_exact(acc[nt][2] + bb.x), gelu_exact(acc[nt][3] + bb.y));
    }
}

__global__ void __launch_bounds__(NTH, 1)
diffusion_kernel(const float* __restrict__ condition,
                 const float* __restrict__ x_init,
                 const float* __restrict__ W1, const float* __restrict__ b1,
                 const float* __restrict__ b2, const float* __restrict__ b3,
                 const float* __restrict__ b4, const int* __restrict__ tsp,
                 float* __restrict__ out)
{
    extern __shared__ char sm[];
    __half* H    = (__half*)(sm + SH_OFF);
    float* sBias = (float*)(sm + SBIAS_OFF);
    float* sC    = (float*)(sm + SCONST_OFF);
    uint32_t sb  = smem_u32(sm);

    int tid = threadIdx.x, w = tid >> 5, lane = tid & 31;
    int gid = lane >> 2, tig = lane & 3;
    int m0 = (w & 3) * 16;         // 4 m-tiles of 16 rows
    int nL = (w >> 2) * 128;       // layers 1-3 col block
    int n4 = (w >> 2) * 32;        // layer 4 / x-fragment col block
    int mA = m0 + gid, mB = m0 + gid + 8;
    int grA = blockIdx.x * MT + mA, grB = blockIdx.x * MT + mB;
    int giA = grA * LAT + n4, giB = grB * LAT + n4;

    if (tid == 0) {
        float acp = 1.0f, bstep = (0.02f - 1e-4f) / 49.0f;
        for (int t = 0; t < NSTEPS; ++t) {
            float beta = fmaf((float)t, bstep, 1e-4f);
            float alpha = 1.0f - beta;
            acp *= alpha;
            sC[t]              = beta / sqrtf(1.0f - acp);
            sC[NSTEPS + t]     = 1.0f / sqrtf(alpha);
            sC[2 * NSTEPS + t] = sqrtf(beta);
        }
    }
    sBias[512 + tid]  = b2[tid];
    sBias[1024 + tid] = b3[tid];
    if (tid < 128) sBias[1536 + tid] = b4[tid];

    // x fragment in registers (C-fragment layout)
    float xr[4][4];
#pragma unroll
    for (int nt = 0; nt < 4; ++nt) {
        int n = n4 + nt * 8 + tig * 2;
        float2 v0 = *(const float2*)(x_init + (size_t)grA * LAT + n);
        float2 v1 = *(const float2*)(x_init + (size_t)grB * LAT + n);
        xr[nt][0] = v0.x; xr[nt][1] = v0.y; xr[nt][2] = v1.x; xr[nt][3] = v1.y;
    }
    float tgt = (*tsp) ? 0.0f : 1.0f;

    // initial prefetch: layer-1 chunk 0 -> buf 0
    wload(sb, 0u, g_WT + WT1_OFF, 512, 256, tid);

    for (int t = NSTEPS - 1; t >= 0; --t) {
        float tval = (float)t / (float)NSTEPS;
        // fold t_emb / target columns into layer-1 bias (fp32 exact)
        sBias[tid] = b1[tid] + tval * W1[256 * HID + tid] + tgt * W1[257 * HID + tid];

        uint32_t fk0 = 0, fk1 = 0;
        bool dorng = (t > 0);
        if (dorng) threefry2x32(0u, 42u, 0u, (uint32_t)t, fk0, fk1);
        float nz[16];
        if (!dorng) {
#pragma unroll
            for (int i = 0; i < 16; ++i) nz[i] = 0.0f;
        }

        // rebuild layer-1 input in H[:, 0:256]: x (regs) | condition (L2 reload)
#pragma unroll
        for (int nt = 0; nt < 4; ++nt) {
            int n = n4 + nt * 8 + tig * 2;
            *(__half2*)(H + mA * SHS + n) = __floats2half2_rn(xr[nt][0], xr[nt][1]);
            *(__half2*)(H + mB * SHS + n) = __floats2half2_rn(xr[nt][2], xr[nt][3]);
            float2 c0 = *(const float2*)(condition + (size_t)grA * LAT + n);
            float2 c1 = *(const float2*)(condition + (size_t)grB * LAT + n);
            *(__half2*)(H + mA * SHS + 128 + n) = __floats2half2_rn(c0.x, c0.y);
            *(__half2*)(H + mB * SHS + 128 + n) = __floats2half2_rn(c1.x, c1.y);
        }
        // (layer_mma's first __syncthreads orders these writes before MMA reads)

        float acc[16][4];
#pragma unroll
        for (int i = 0; i < 16; ++i) { acc[i][0]=acc[i][1]=acc[i][2]=acc[i][3]=0.f; }
        layer_mma<256, 16>(sm, sb, g_WT + WT1_OFF, 512, g_WT + WT2_OFF, 512, 512,
                           H, acc, tid, gid, tig, m0, nL, false, nz, 0, 0, 0, 0);
        epi_gelu<16>(acc, H, sBias, m0, nL, gid, tig);

#pragma unroll
        for (int i = 0; i < 16; ++i) { acc[i][0]=acc[i][1]=acc[i][2]=acc[i][3]=0.f; }
        layer_mma<512, 16>(sm, sb, g_WT + WT2_OFF, 512, g_WT + WT3_OFF, 512, 512,
                           H, acc, tid, gid, tig, m0, nL, false, nz, 0, 0, 0, 0);
        epi_gelu<16>(acc, H, sBias + 512, m0, nL, gid, tig);

#pragma unroll
        for (int i = 0; i < 16; ++i) { acc[i][0]=acc[i][1]=acc[i][2]=acc[i][3]=0.f; }
        layer_mma<512, 16>(sm, sb, g_WT + WT3_OFF, 512, g_WT + WT4_OFF, 128, 512,
                           H, acc, tid, gid, tig, m0, nL, dorng, nz, fk0, fk1, giA, giB);
        epi_gelu<16>(acc, H, sBias + 1024, m0, nL, gid, tig);

        float a4[4][4];
#pragma unroll
        for (int i = 0; i < 4; ++i) { a4[i][0]=a4[i][1]=a4[i][2]=a4[i][3]=0.f; }
        layer_mma<512, 4>(sm, sb, g_WT + WT4_OFF, 128, g_WT + WT1_OFF, 512, 256,
                          H, a4, tid, gid, tig, m0, n4, false, nz, 0, 0, 0, 0);

        // x update (noise already in nz[] from layer-3 interleave)
        float c1 = sC[t], isa = sC[NSTEPS + t], sbeta = sC[2 * NSTEPS + t];
#pragma unroll
        for (int nt = 0; nt < 4; ++nt) {
            int n = n4 + nt * 8 + tig * 2;
            float2 bb = *(const float2*)(sBias + 1536 + n);
            xr[nt][0] = (xr[nt][0] - c1 * (a4[nt][0] + bb.x)) * isa + sbeta * nz[nt*4+0];
            xr[nt][1] = (xr[nt][1] - c1 * (a4[nt][1] + bb.y)) * isa + sbeta * nz[nt*4+1];
            xr[nt][2] = (xr[nt][2] - c1 * (a4[nt][2] + bb.x)) * isa + sbeta * nz[nt*4+2];
            xr[nt][3] = (xr[nt][3] - c1 * (a4[nt][3] + bb.y)) * isa + sbeta * nz[nt*4+3];
        }
        __syncthreads();   // H reads (layer4) done before next step's H writes
    }

#pragma unroll
    for (int nt = 0; nt < 4; ++nt) {
        int n = n4 + nt * 8 + tig * 2;
        *(float2*)(out + (size_t)grA * LAT + n) = make_float2(xr[nt][0], xr[nt][1]);
        *(float2*)(out + (size_t)grB * LAT + n) = make_float2(xr[nt][2], xr[nt][3]);
    }
}

extern "C" void kernel_launch(void* const* d_in, const int* in_sizes, int n_in,
                              void* d_out, int out_size) {
    const float* condition = (const float*)d_in[0];
    const float* x_init    = (const float*)d_in[1];
    const float* W1 = (const float*)d_in[2];
    const float* b1 = (const float*)d_in[3];
    const float* W2 = (const float*)d_in[4];
    const float* b2 = (const float*)d_in[5];
    const float* W3 = (const float*)d_in[6];
    const float* b3 = (const float*)d_in[7];
    const float* W4 = (const float*)d_in[8];
    const float* b4 = (const float*)d_in[9];
    const int*   ts = (const int*)d_in[10];
    float* out = (float*)d_out;

    prep_kernel<<<(WT_TOT + 255) / 256, 256>>>(W1, W2, W3, W4);

    cudaFuncSetAttribute(diffusion_kernel,
                         cudaFuncAttributeMaxDynamicSharedMemorySize, SMEM_TOTAL);
    diffusion_kernel<<<NCTAS, NTH, SMEM_TOTAL>>>(
        condition, x_init, W1, b1, b2, b3, b4, ts, out);
}

// round 9
// speedup vs baseline: 2.1099x; 1.3093x over previous
#include <cuda_runtime.h>
#include <cuda_fp16.h>
#include <stdint.h>
#include <math.h>

#define LAT     128
#define HID     512
#define NSTEPS  50
#define NTH     512
#define MT      64
#define NCTAS   128

#define SHS     520      // H stride in halfs (1040 B ≡ 16 mod 128: ldmatrix conflict-free)
#define SWK     72       // W chunk stride in halfs (144 B ≡ 16 mod 128: ldmatrix conflict-free)

// SMEM byte offsets
#define SH_OFF    0                // H: 64 x 520 halfs = 66560 B
#define SW_OFF    66560            // W double buffer: 2 x 512 x 72 halfs
#define SW_BUF    73728
#define SBIAS_OFF 214016           // f32: b1eff[512] b2[512] b3[512] b4[128]
#define SCONST_OFF 220672          // f32: c1[50] isa[50] sqrtbeta[50]
#define SMEM_TOTAL 221312

// fp16 transposed weights WT[n][k] (K contiguous)
#define WT1_OFF 0                  // [512][256]
#define WT2_OFF 131072             // [512][512]
#define WT3_OFF 393216             // [512][512]
#define WT4_OFF 655360             // [128][512]
#define WT_TOT  720896
__device__ __align__(16) __half g_WT[WT_TOT];

// ---------------- PTX helpers ----------------
__device__ __forceinline__ uint32_t smem_u32(const void* p) {
    uint32_t a;
    asm("{ .reg .u64 t; cvta.to.shared.u64 t, %1; cvt.u32.u64 %0, t; }" : "=r"(a) : "l"(p));
    return a;
}
__device__ __forceinline__ void cpasync16(uint32_t dst, const void* src) {
    asm volatile("cp.async.cg.shared.global [%0], [%1], 16;\n" :: "r"(dst), "l"(src));
}
#define CP_COMMIT() asm volatile("cp.async.commit_group;\n" ::: "memory")
#define CP_WAIT0()  asm volatile("cp.async.wait_group 0;\n" ::: "memory")
#define BARP(id)    asm volatile("bar.sync %0, 64;" :: "r"(id) : "memory")

__device__ __forceinline__ void ldsm4(uint32_t r[4], uint32_t a) {
    asm volatile("ldmatrix.sync.aligned.m8n8.x4.shared.b16 {%0,%1,%2,%3}, [%4];"
                 : "=r"(r[0]), "=r"(r[1]), "=r"(r[2]), "=r"(r[3]) : "r"(a));
}
__device__ __forceinline__ void mma16816(float d[4], const uint32_t a[4], const uint32_t* b) {
    asm volatile(
        "mma.sync.aligned.m16n8k16.row.col.f32.f16.f16.f32 "
        "{%0,%1,%2,%3}, {%4,%5,%6,%7}, {%8,%9}, {%0,%1,%2,%3};\n"
        : "+f"(d[0]), "+f"(d[1]), "+f"(d[2]), "+f"(d[3])
        : "r"(a[0]), "r"(a[1]), "r"(a[2]), "r"(a[3]), "r"(b[0]), "r"(b[1]));
}

// ---------------- JAX threefry + erfinv (bit-proven round 2) ----------------
__device__ __forceinline__ uint32_t rotl32(uint32_t x, uint32_t r) {
    return __funnelshift_l(x, x, r);
}
__device__ __forceinline__ void threefry2x32(uint32_t k0, uint32_t k1,
                                             uint32_t c0, uint32_t c1,
                                             uint32_t& o0, uint32_t& o1) {
    uint32_t ks2 = k0 ^ k1 ^ 0x1BD11BDAu;
    uint32_t x0 = c0 + k0, x1 = c1 + k1;
#define TF_RND(r) { x0 += x1; x1 = rotl32(x1, r); x1 ^= x0; }
    TF_RND(13) TF_RND(15) TF_RND(26) TF_RND(6)
    x0 += k1;  x1 += ks2 + 1u;
    TF_RND(17) TF_RND(29) TF_RND(16) TF_RND(24)
    x0 += ks2; x1 += k0 + 2u;
    TF_RND(13) TF_RND(15) TF_RND(26) TF_RND(6)
    x0 += k0;  x1 += k1 + 3u;
    TF_RND(17) TF_RND(29) TF_RND(16) TF_RND(24)
    x0 += k1;  x1 += ks2 + 4u;
    TF_RND(13) TF_RND(15) TF_RND(26) TF_RND(6)
    x0 += ks2; x1 += k0 + 5u;
#undef TF_RND
    o0 = x0; o1 = x1;
}
__device__ __forceinline__ float erfinv_f32(float x) {
    float w = -log1pf(-x * x), p;
    if (w < 5.0f) {
        w -= 2.5f;
        p = 2.81022636e-08f;
        p = fmaf(p, w, 3.43273939e-07f);  p = fmaf(p, w, -3.5233877e-06f);
        p = fmaf(p, w, -4.39150654e-06f); p = fmaf(p, w, 0.00021858087f);
        p = fmaf(p, w, -0.00125372503f);  p = fmaf(p, w, -0.00417768164f);
        p = fmaf(p, w, 0.246640727f);     p = fmaf(p, w, 1.50140941f);
    } else {
        w = sqrtf(w) - 3.0f;
        p = -0.000200214257f;
        p = fmaf(p, w, 0.000100950558f);  p = fmaf(p, w, 0.00134934322f);
        p = fmaf(p, w, -0.00367342844f);  p = fmaf(p, w, 0.00573950773f);
        p = fmaf(p, w, -0.0076224613f);   p = fmaf(p, w, 0.00943887047f);
        p = fmaf(p, w, 1.00167406f);      p = fmaf(p, w, 2.83297682f);
    }
    return p * x;
}
__device__ __forceinline__ float jax_normal(uint32_t fk0, uint32_t fk1, uint32_t gi) {
    uint32_t o0, o1;
    threefry2x32(fk0, fk1, 0u, gi, o0, o1);
    uint32_t bits = o0 ^ o1;
    float f = __uint_as_float((bits >> 9) | 0x3f800000u) - 1.0f;
    float u = fmaxf(fmaf(f, 2.0f, -0.99999994f), -0.99999994f);
    return 1.4142135623730951f * erfinv_f32(u);
}
__device__ __forceinline__ float gelu_exact(float v) {
    return 0.5f * v * (1.0f + erff(v * 0.7071067811865476f));
}

// ---------------- weight prep: fp32 -> fp16 transposed (K contiguous) -------
__global__ void prep_kernel(const float* __restrict__ W1, const float* __restrict__ W2,
                            const float* __restrict__ W3, const float* __restrict__ W4) {
    int i = blockIdx.x * 256 + threadIdx.x;
    if (i < 512*256) { int n=i/256, k=i%256; g_WT[WT1_OFF+i] = __float2half_rn(W1[k*512+n]); return; }
    i -= 512*256;
    if (i < 512*512) { int n=i/512, k=i%512; g_WT[WT2_OFF+i] = __float2half_rn(W2[k*512+n]); return; }
    i -= 512*512;
    if (i < 512*512) { int n=i/512, k=i%512; g_WT[WT3_OFF+i] = __float2half_rn(W3[k*512+n]); return; }
    i -= 512*512;
    if (i < 128*512) { int n=i/512, k=i%512; g_WT[WT4_OFF+i] = __float2half_rn(W4[k*128+n]); return; }
}

// pair-local W slice loader: pair ng loads ONLY the rows it will itself read.
__device__ __forceinline__ void wload_pair(uint32_t sb, uint32_t boff,
                                           const __half* __restrict__ src,
                                           int kdim, int grows, int ng, int ptid) {
    int base = ng * grows;
    for (int v = ptid; v < grows * 8; v += 64) {
        int r = v >> 3, kp = v & 7;
        int row = base + r;
        cpasync16(sb + SW_OFF + boff + (uint32_t)(row * SWK + kp * 8) * 2,
                  src + (size_t)row * kdim + kp * 8);
    }
    CP_COMMIT();
}

// ---------------- one layer: K=64 chunks, pair-synced, ldmatrix fragments ---
// Intra-layer prefetch ONLY (pair's own rows) — cross-layer chunk-0 loads are
// issued by the caller after a CTA-wide __syncthreads (race-free by ownership).
template<int KDIM, int NT>
__device__ __forceinline__ void layer_mma(uint32_t sb, uint32_t aAddr, uint32_t bOff,
        const __half* __restrict__ WTg, int grows,
        float (&acc)[2][NT][4], int ptid, int ng, int barid,
        bool dorng, float* nz, uint32_t fk0, uint32_t fk1, int grow0, int n4t)
{
    constexpr int C = KDIM / 64;
    for (int c = 0; c < C; ++c) {
        CP_WAIT0();
        BARP(barid);
        if (c + 1 < C)
            wload_pair(sb, (uint32_t)(((c + 1) & 1) * SW_BUF), WTg + (c + 1) * 64,
                       KDIM, grows, ng, ptid);
        uint32_t wb = sb + SW_OFF + (uint32_t)((c & 1) * SW_BUF) + bOff;
#pragma unroll
        for (int ks = 0; ks < 4; ++ks) {
            int k0 = c * 64 + ks * 16;
            uint32_t a0[4], a1[4];
            ldsm4(a0, aAddr + (uint32_t)(k0 * 2));
            ldsm4(a1, aAddr + (uint32_t)((16 * SHS + k0) * 2));
#pragma unroll
            for (int ntp = 0; ntp < NT / 2; ++ntp) {
                uint32_t b[4];
                ldsm4(b, wb + (uint32_t)((ntp * 16 * SWK + ks * 16) * 2));
                mma16816(acc[0][2 * ntp],     a0, b);
                mma16816(acc[0][2 * ntp + 1], a0, b + 2);
                mma16816(acc[1][2 * ntp],     a1, b);
                mma16816(acc[1][2 * ntp + 1], a1, b + 2);
            }
        }
        if (dorng) {   // layer3 only: C=8 chunks x 2 normals = all 16
#pragma unroll
            for (int q = 0; q < 2; ++q) {
                int idx = 2 * c + q;
                int mt = idx >> 3, ntl = (idx >> 2) & 1, j = idx & 3;
                int row = grow0 + mt * 16 + ((j >> 1) ? 8 : 0);
                nz[idx] = jax_normal(fk0, fk1, (uint32_t)(row * LAT + n4t + ntl * 8 + (j & 1)));
            }
        }
    }
}

// epilogue: acc + bias -> gelu -> fp16 H (after CTA sync; in-place safe)
template<int NT>
__device__ __forceinline__ void epi_gelu(float (&acc)[2][NT][4], __half* Hout,
                                         const float* bias, int m0, int n0,
                                         int gid, int tig)
{
#pragma unroll
    for (int mt = 0; mt < 2; ++mt) {
        int rA = m0 + mt * 16 + gid, rB = rA + 8;
#pragma unroll
        for (int nt = 0; nt < NT; ++nt) {
            int n = n0 + nt * 8 + tig * 2;
            float2 bb = *(const float2*)(bias + n);
            *(__half2*)(Hout + rA * SHS + n) =
                __floats2half2_rn(gelu_exact(acc[mt][nt][0] + bb.x), gelu_exact(acc[mt][nt][1] + bb.y));
            *(__half2*)(Hout + rB * SHS + n) =
                __floats2half2_rn(gelu_exact(acc[mt][nt][2] + bb.x), gelu_exact(acc[mt][nt][3] + bb.y));
        }
    }
}

__global__ void __launch_bounds__(NTH, 1)
diffusion_kernel(const float* __restrict__ condition,
                 const float* __restrict__ x_init,
                 const float* __restrict__ W1, const float* __restrict__ b1,
                 const float* __restrict__ b2, const float* __restrict__ b3,
                 const float* __restrict__ b4, const int* __restrict__ tsp,
                 float* __restrict__ out)
{
    extern __shared__ char sm[];
    __half* H    = (__half*)(sm + SH_OFF);
    float* sBias = (float*)(sm + SBIAS_OFF);
    float* sC    = (float*)(sm + SCONST_OFF);
    uint32_t sb  = smem_u32(sm);

    int tid = threadIdx.x, w = tid >> 5, lane = tid & 31;
    int gid = lane >> 2, tig = lane & 3;
    int sel = lane >> 3, low3 = lane & 7;
    int mg = w & 1, ng = w >> 1;
    int m0 = mg * 32;             // warp rows m0..m0+31 (2 m16 tiles)
    int n0 = ng * 64;             // layers 1-3 col block
    int n4 = ng * 16;             // layer 4 / x-fragment col block
    int ptid = mg * 32 + lane;    // id within warp pair
    int barid = 1 + ng;           // named barrier per pair
    int grow0 = blockIdx.x * MT + m0 + gid;
    int n4t = n4 + tig * 2;

    // per-lane ldmatrix base addresses
    uint32_t aAddr = sb + SH_OFF +
        (uint32_t)(((m0 + (sel & 1) * 8 + low3) * SHS + (sel >> 1) * 8) * 2);
    uint32_t bOffL = (uint32_t)(((n0 + (sel >> 1) * 8 + low3) * SWK + (sel & 1) * 8) * 2);
    uint32_t bOff4 = (uint32_t)(((n4 + (sel >> 1) * 8 + low3) * SWK + (sel & 1) * 8) * 2);

    if (tid == 0) {
        float acp = 1.0f, bstep = (0.02f - 1e-4f) / 49.0f;
        for (int t = 0; t < NSTEPS; ++t) {
            float beta = fmaf((float)t, bstep, 1e-4f);
            float alpha = 1.0f - beta;
            acp *= alpha;
            sC[t]              = beta / sqrtf(1.0f - acp);
            sC[NSTEPS + t]     = 1.0f / sqrtf(alpha);
            sC[2 * NSTEPS + t] = sqrtf(beta);
        }
    }
    sBias[512 + tid]  = b2[tid];
    sBias[1024 + tid] = b3[tid];
    if (tid < 128) sBias[1536 + tid] = b4[tid];

    // x fragment in registers: xr[mt][ntl][4]
    float xr[2][2][4];
#pragma unroll
    for (int mt = 0; mt < 2; ++mt) {
        int rA = grow0 + mt * 16, rB = rA + 8;
#pragma unroll
        for (int ntl = 0; ntl < 2; ++ntl) {
            int n = n4t + ntl * 8;
            float2 v0 = *(const float2*)(x_init + (size_t)rA * LAT + n);
            float2 v1 = *(const float2*)(x_init + (size_t)rB * LAT + n);
            xr[mt][ntl][0] = v0.x; xr[mt][ntl][1] = v0.y;
            xr[mt][ntl][2] = v1.x; xr[mt][ntl][3] = v1.y;
        }
    }
    float tgt = (*tsp) ? 0.0f : 1.0f;

    // initial prefetch: layer-1 chunk 0 -> buf 0 (pair's own slice)
    wload_pair(sb, 0u, g_WT + WT1_OFF, 256, 64, ng, ptid);

    for (int t = NSTEPS - 1; t >= 0; --t) {
        float tval = (float)t / (float)NSTEPS;
        sBias[tid] = b1[tid] + tval * W1[256 * HID + tid] + tgt * W1[257 * HID + tid];

        uint32_t fk0 = 0, fk1 = 0;
        bool dorng = (t > 0);
        if (dorng) threefry2x32(0u, 42u, 0u, (uint32_t)t, fk0, fk1);
        float nz[16];
        if (!dorng) {
#pragma unroll
            for (int i = 0; i < 16; ++i) nz[i] = 0.0f;
        }

        // rebuild layer-1 input H[:,0:256]: x (regs) | condition (L2 reload)
#pragma unroll
        for (int mt = 0; mt < 2; ++mt) {
            int rA = m0 + mt * 16 + gid, rB = rA + 8;
            int gA = grow0 + mt * 16, gB = gA + 8;
#pragma unroll
            for (int ntl = 0; ntl < 2; ++ntl) {
                int n = n4t + ntl * 8;
                *(__half2*)(H + rA * SHS + n) = __floats2half2_rn(xr[mt][ntl][0], xr[mt][ntl][1]);
                *(__half2*)(H + rB * SHS + n) = __floats2half2_rn(xr[mt][ntl][2], xr[mt][ntl][3]);
                float2 c0 = *(const float2*)(condition + (size_t)gA * LAT + n);
                float2 c1 = *(const float2*)(condition + (size_t)gB * LAT + n);
                *(__half2*)(H + rA * SHS + 128 + n) = __floats2half2_rn(c0.x, c0.y);
                *(__half2*)(H + rB * SHS + 128 + n) = __floats2half2_rn(c1.x, c1.y);
            }
        }
        __syncthreads();   // s1: H + L1-bias ready for all warps

        float acc[2][8][4];
#pragma unroll
        for (int mt = 0; mt < 2; ++mt)
#pragma unroll
            for (int i = 0; i < 8; ++i)
                acc[mt][i][0]=acc[mt][i][1]=acc[mt][i][2]=acc[mt][i][3]=0.f;
        layer_mma<256, 8>(sb, aAddr, bOffL, g_WT + WT1_OFF, 64,
                          acc, ptid, ng, barid, false, nz, 0, 0, 0, 0);
        __syncthreads();   // s2: all buffer/A reads done CTA-wide
        wload_pair(sb, 0u, g_WT + WT2_OFF, 512, 64, ng, ptid);   // L2 chunk0 (own rows)
        epi_gelu<8>(acc, H, sBias, m0, n0, gid, tig);
        __syncthreads();   // s3

#pragma unroll
        for (int mt = 0; mt < 2; ++mt)
#pragma unroll
            for (int i = 0; i < 8; ++i)
                acc[mt][i][0]=acc[mt][i][1]=acc[mt][i][2]=acc[mt][i][3]=0.f;
        layer_mma<512, 8>(sb, aAddr, bOffL, g_WT + WT2_OFF, 64,
                          acc, ptid, ng, barid, false, nz, 0, 0, 0, 0);
        __syncthreads();   // s4
        wload_pair(sb, 0u, g_WT + WT3_OFF, 512, 64, ng, ptid);   // L3 chunk0
        epi_gelu<8>(acc, H, sBias + 512, m0, n0, gid, tig);
        __syncthreads();   // s5

#pragma unroll
        for (int mt = 0; mt < 2; ++mt)
#pragma unroll
            for (int i = 0; i < 8; ++i)
                acc[mt][i][0]=acc[mt][i][1]=acc[mt][i][2]=acc[mt][i][3]=0.f;
        layer_mma<512, 8>(sb, aAddr, bOffL, g_WT + WT3_OFF, 64,
                          acc, ptid, ng, barid, dorng, nz, fk0, fk1, grow0, n4t);
        __syncthreads();   // s6
        wload_pair(sb, 0u, g_WT + WT4_OFF, 512, 16, ng, ptid);   // L4 chunk0 (own 16 rows)
        epi_gelu<8>(acc, H, sBias + 1024, m0, n0, gid, tig);
        __syncthreads();   // s7

        float a4[2][2][4];
#pragma unroll
        for (int mt = 0; mt < 2; ++mt)
#pragma unroll
            for (int i = 0; i < 2; ++i)
                a4[mt][i][0]=a4[mt][i][1]=a4[mt][i][2]=a4[mt][i][3]=0.f;
        layer_mma<512, 2>(sb, aAddr, bOff4, g_WT + WT4_OFF, 16,
                          a4, ptid, ng, barid, false, nz, 0, 0, 0, 0);

        // x update (noise already in nz[] from layer-3 interleave)
        float c1 = sC[t], isa = sC[NSTEPS + t], sbeta = sC[2 * NSTEPS + t];
#pragma unroll
        for (int mt = 0; mt < 2; ++mt)
#pragma unroll
            for (int ntl = 0; ntl < 2; ++ntl) {
                int n = n4t + ntl * 8;
                float2 bb = *(const float2*)(sBias + 1536 + n);
                int ib = mt * 8 + ntl * 4;
                xr[mt][ntl][0] = (xr[mt][ntl][0] - c1 * (a4[mt][ntl][0] + bb.x)) * isa + sbeta * nz[ib + 0];
                xr[mt][ntl][1] = (xr[mt][ntl][1] - c1 * (a4[mt][ntl][1] + bb.y)) * isa + sbeta * nz[ib + 1];
                xr[mt][ntl][2] = (xr[mt][ntl][2] - c1 * (a4[mt][ntl][2] + bb.x)) * isa + sbeta * nz[ib + 2];
                xr[mt][ntl][3] = (xr[mt][ntl][3] - c1 * (a4[mt][ntl][3] + bb.y)) * isa + sbeta * nz[ib + 3];
            }
        __syncthreads();   // s8: all L4 buffer/H reads done CTA-wide
        wload_pair(sb, 0u, g_WT + WT1_OFF, 256, 64, ng, ptid);   // next step L1 chunk0
    }

#pragma unroll
    for (int mt = 0; mt < 2; ++mt) {
        int gA = grow0 + mt * 16, gB = gA + 8;
#pragma unroll
        for (int ntl = 0; ntl < 2; ++ntl) {
            int n = n4t + ntl * 8;
            *(float2*)(out + (size_t)gA * LAT + n) = make_float2(xr[mt][ntl][0], xr[mt][ntl][1]);
            *(float2*)(out + (size_t)gB * LAT + n) = make_float2(xr[mt][ntl][2], xr[mt][ntl][3]);
        }
    }
}

extern "C" void kernel_launch(void* const* d_in, const int* in_sizes, int n_in,
                              void* d_out, int out_size) {
    const float* condition = (const float*)d_in[0];
    const float* x_init    = (const float*)d_in[1];
    const float* W1 = (const float*)d_in[2];
    const float* b1 = (const float*)d_in[3];
    const float* W2 = (const float*)d_in[4];
    const float* b2 = (const float*)d_in[5];
    const float* W3 = (const float*)d_in[6];
    const float* b3 = (const float*)d_in[7];
    const float* W4 = (const float*)d_in[8];
    const float* b4 = (const float*)d_in[9];
    const int*   ts = (const int*)d_in[10];
    float* out = (float*)d_out;

    prep_kernel<<<(WT_TOT + 255) / 256, 256>>>(W1, W2, W3, W4);

    cudaFuncSetAttribute(diffusion_kernel,
                         cudaFuncAttributeMaxDynamicSharedMemorySize, SMEM_TOTAL);
    diffusion_kernel<<<NCTAS, NTH, SMEM_TOTAL>>>(
        condition, x_init, W1, b1, b2, b3, b4, ts, out);
}